// round 1
// baseline (speedup 1.0000x reference)
#include <cuda_runtime.h>
#include <cstdint>

// Sinkhorn: B=8, N=2048, eps=0.01, 50 fused (u,v) iterations.
// u_new_i = eps*(log_mu - LSE_j((c_ij + v_j)/eps))        (old u cancels)
// v_new_j = eps*(log_mu - LSE_i((c_ij + u_new_i)/eps))    (old v cancels)
// All LSE done in base-2: x = c*S + w, S = 1/(eps*ln2).
// Outputs: [pi (B*N*N), -c (B*N*N), u (B*N), v (B*N)]

#define NN 2048
#define SINK_S  144.26950408889634f     // 1/(eps*ln2) = 100*log2(e)
#define SINK_C0 -0.07624618986159398f   // eps*log_mu = -0.01*ln(2048)
#define SINK_C1 0.006931471805599453f   // eps*ln2

__device__ float g_u[8 * NN];
__device__ float g_v[8 * NN];

__device__ __forceinline__ float ex2f(float x) {
    float r; asm("ex2.approx.f32 %0, %1;" : "=f"(r) : "f"(x)); return r;
}
__device__ __forceinline__ float lg2f(float x) {
    float r; asm("lg2.approx.f32 %0, %1;" : "=f"(r) : "f"(x)); return r;
}

// Branchless online LSE step (one MUFU per element).
__device__ __forceinline__ void lse_step(float x, float& m, float& s) {
    float d = x - m;
    float t = ex2f(-fabsf(d));
    bool p = (d >= 0.0f);
    float a  = p ? t    : 1.0f;
    float bb = p ? 1.0f : t;
    s = fmaf(s, a, bb);
    m = fmaxf(m, x);
}

// Combine two (m, s) partials.
__device__ __forceinline__ void lse_combine(float m2, float s2, float& m, float& s) {
    float mm = fmaxf(m, m2);
    s = fmaf(s, ex2f(m - mm), s2 * ex2f(m2 - mm));
    m = mm;
}

__global__ void __launch_bounds__(256) init_kernel(int B) {
    int i = blockIdx.x * 256 + threadIdx.x;
    if (i < B * NN) g_v[i] = 0.0f;
}

// ---- u-pass: one warp per row, reduce over columns j ----
__global__ void __launch_bounds__(256) upass_kernel(const float* __restrict__ c) {
    __shared__ float sw[NN];
    const int b  = blockIdx.x / (NN / 8);
    const int r0 = (blockIdx.x % (NN / 8)) * 8;
    for (int j = threadIdx.x; j < NN; j += 256)
        sw[j] = g_v[b * NN + j] * SINK_S;
    __syncthreads();

    const int warp = threadIdx.x >> 5, lane = threadIdx.x & 31;
    const int row = r0 + warp;
    const float4* __restrict__ crow =
        reinterpret_cast<const float4*>(c + ((size_t)b * NN + row) * NN);
    const float4* wrow = reinterpret_cast<const float4*>(sw);

    float m = -1e30f, s = 0.0f;
    #pragma unroll 4
    for (int t = lane; t < NN / 4; t += 32) {
        float4 cc = crow[t];
        float4 ww = wrow[t];
        lse_step(fmaf(cc.x, SINK_S, ww.x), m, s);
        lse_step(fmaf(cc.y, SINK_S, ww.y), m, s);
        lse_step(fmaf(cc.z, SINK_S, ww.z), m, s);
        lse_step(fmaf(cc.w, SINK_S, ww.w), m, s);
    }
    #pragma unroll
    for (int off = 16; off; off >>= 1) {
        float m2 = __shfl_down_sync(0xffffffffu, m, off);
        float s2 = __shfl_down_sync(0xffffffffu, s, off);
        lse_combine(m2, s2, m, s);
    }
    if (lane == 0) {
        float lse2 = m + lg2f(s);
        g_u[b * NN + row] = fmaf(-SINK_C1, lse2, SINK_C0);
    }
}

// ---- v-pass: column-parallel, warps split rows into 8 chunks ----
// CTA: 256 threads = 8 warps; each warp covers 64 columns (lane owns 2 via
// float2) over a 256-row chunk. Grid = B * (N/64) = 256 CTAs.
__global__ void __launch_bounds__(256) vpass_kernel(const float* __restrict__ c) {
    __shared__ float su[NN];
    __shared__ float red_m[8][64];
    __shared__ float red_s[8][64];
    const int b  = blockIdx.x / (NN / 64);
    const int j0 = (blockIdx.x % (NN / 64)) * 64;
    for (int i = threadIdx.x; i < NN; i += 256)
        su[i] = g_u[b * NN + i] * SINK_S;
    __syncthreads();

    const int warp = threadIdx.x >> 5, lane = threadIdx.x & 31;
    const int i0 = warp * (NN / 8);
    const float* __restrict__ cbase =
        c + ((size_t)b * NN + i0) * NN + j0 + lane * 2;

    float m0 = -1e30f, s0 = 0.0f, m1 = -1e30f, s1 = 0.0f;
    #pragma unroll 4
    for (int i = 0; i < NN / 8; i++) {
        float uu = su[i0 + i];
        float2 cc = *reinterpret_cast<const float2*>(cbase + (size_t)i * NN);
        lse_step(fmaf(cc.x, SINK_S, uu), m0, s0);
        lse_step(fmaf(cc.y, SINK_S, uu), m1, s1);
    }
    red_m[warp][lane * 2]     = m0;
    red_m[warp][lane * 2 + 1] = m1;
    red_s[warp][lane * 2]     = s0;
    red_s[warp][lane * 2 + 1] = s1;
    __syncthreads();

    if (threadIdx.x < 64) {
        const int col = threadIdx.x;
        float m = -1e30f, s = 0.0f;
        #pragma unroll
        for (int k = 0; k < 8; k++)
            lse_combine(red_m[k][col], red_s[k][col], m, s);
        float vv = fmaf(-SINK_C1, m + lg2f(s), SINK_C0);
        if (vv > 9e8f) vv = 0.0f;   // reference clamp (never triggers in practice)
        g_v[b * NN + j0 + col] = vv;
    }
}

// ---- epilogue: pi = exp((c+u+v)/eps), -c, u, v ----
__global__ void __launch_bounds__(128) final_kernel(const float* __restrict__ c,
                                                    float* __restrict__ out, int B) {
    const size_t BNN = (size_t)B * NN * NN;
    const int rowid = blockIdx.x;          // 0 .. B*N-1
    const int b = rowid >> 11;             // / N
    const float u = g_u[rowid];
    const float4* __restrict__ crow =
        reinterpret_cast<const float4*>(c + (size_t)rowid * NN);
    const float4* __restrict__ vrow =
        reinterpret_cast<const float4*>(g_v + (size_t)b * NN);
    float4* pio = reinterpret_cast<float4*>(out + (size_t)rowid * NN);
    float4* nco = reinterpret_cast<float4*>(out + BNN + (size_t)rowid * NN);

    #pragma unroll 2
    for (int t = threadIdx.x; t < NN / 4; t += 128) {
        float4 cc = crow[t];
        float4 vv = vrow[t];
        float4 pi, nc;
        pi.x = ex2f(((cc.x + u) + vv.x) * SINK_S);
        pi.y = ex2f(((cc.y + u) + vv.y) * SINK_S);
        pi.z = ex2f(((cc.z + u) + vv.z) * SINK_S);
        pi.w = ex2f(((cc.w + u) + vv.w) * SINK_S);
        nc.x = -cc.x; nc.y = -cc.y; nc.z = -cc.z; nc.w = -cc.w;
        pio[t] = pi;
        nco[t] = nc;
    }
    int gid = blockIdx.x * 128 + threadIdx.x;
    if (gid < B * NN) {
        out[2 * BNN + gid] = g_u[gid];
        out[2 * BNN + (size_t)B * NN + gid] = g_v[gid];
    }
}

extern "C" void kernel_launch(void* const* d_in, const int* in_sizes, int n_in,
                              void* d_out, int out_size) {
    const float* c = (const float*)d_in[0];
    const int B = in_sizes[0] / (NN * NN);   // 8

    init_kernel<<<(B * NN + 255) / 256, 256>>>(B);
    for (int it = 0; it < 50; ++it) {
        upass_kernel<<<B * (NN / 8), 256>>>(c);
        vpass_kernel<<<B * (NN / 64), 256>>>(c);
    }
    final_kernel<<<B * NN, 128>>>(c, (float*)d_out, B);
}

// round 5
// speedup vs baseline: 1.3300x; 1.3300x over previous
#include <cuda_runtime.h>
#include <cstdint>

// Sinkhorn: B=8, N=2048, eps=0.01, 50 fused (u,v) iterations.
//   u_i = eps*(log_mu - LSE_j((c_ij + v_j)/eps))   (old u cancels)
//   v_j = eps*(log_mu - LSE_i((c_ij + u_i)/eps))   (old v cancels)
// Base-2 domain: x = c*S + w*S, S = 1/(eps*ln2).
// v-pass runs on a materialized transpose so both passes are coalesced
// warp-per-row reductions with front-batched loads (MLP=16) and a
// two-phase (max tree, then exp2-sum) LSE.
// ALL __device__ scratch symbols are referenced from device code only
// (host code cannot pass a __device__ symbol as a kernel argument).
// Outputs: [pi (B*N*N), -c (B*N*N), u (B*N), v (B*N)]

#define NN 2048
#define BB 8
#define SINK_S  144.26950408889634f     // 1/(eps*ln2) = 100*log2(e)
#define SINK_C0 -0.07624618986159398f   // eps*log_mu = -0.01*ln(2048)
#define SINK_C1 0.006931471805599453f   // eps*ln2

__device__ float g_u[BB * NN];
__device__ float g_v[BB * NN];
__device__ float g_ct[(size_t)BB * NN * NN];   // c transposed per batch

__device__ __forceinline__ float ex2f(float x) {
    float r; asm("ex2.approx.f32 %0, %1;" : "=f"(r) : "f"(x)); return r;
}
__device__ __forceinline__ float lg2f(float x) {
    float r; asm("lg2.approx.f32 %0, %1;" : "=f"(r) : "f"(x)); return r;
}

__global__ void __launch_bounds__(256) init_kernel() {
    int i = blockIdx.x * 256 + threadIdx.x;
    if (i < BB * NN) g_v[i] = 0.0f;
}

// ---- transpose: g_ct[b][j][i] = c[b][i][j] ----
__global__ void __launch_bounds__(256) transpose_kernel(const float* __restrict__ c) {
    __shared__ float t[32][33];
    const int b = blockIdx.z;
    const size_t base = (size_t)b * NN * NN;
    const int x = blockIdx.x * 32 + threadIdx.x;
    const int y = blockIdx.y * 32 + threadIdx.y;
    #pragma unroll
    for (int j = 0; j < 32; j += 8)
        t[threadIdx.y + j][threadIdx.x] = c[base + (size_t)(y + j) * NN + x];
    __syncthreads();
    const int x2 = blockIdx.y * 32 + threadIdx.x;
    const int y2 = blockIdx.x * 32 + threadIdx.y;
    #pragma unroll
    for (int j = 0; j < 32; j += 8)
        g_ct[base + (size_t)(y2 + j) * NN + x2] = t[threadIdx.x][threadIdx.y + j];
}

// ---- LSE pass. UPASS=true:  mat=c (arg),  vec=g_v, out=g_u.
//                UPASS=false: mat=g_ct,     vec=g_u, out=g_v (with clamp). ----
template <bool UPASS>
__global__ void __launch_bounds__(128) pass_kernel(const float* __restrict__ cmat) {
    __shared__ float sw[NN];
    const int b  = blockIdx.x >> 9;              // / (NN/4)
    const int r0 = (blockIdx.x & 511) * 4;

    const float* vec = UPASS ? g_v : g_u;        // device-side symbol refs
    const float* mat = UPASS ? cmat : g_ct;
    float*       out = UPASS ? g_u : g_v;

    {
        const float4* vv = reinterpret_cast<const float4*>(vec + b * NN);
        float4* sv = reinterpret_cast<float4*>(sw);
        #pragma unroll
        for (int t = threadIdx.x; t < NN / 4; t += 128) {
            float4 w = vv[t];
            w.x *= SINK_S; w.y *= SINK_S; w.z *= SINK_S; w.w *= SINK_S;
            sv[t] = w;
        }
    }
    __syncthreads();

    const int warp = threadIdx.x >> 5, lane = threadIdx.x & 31;
    const int row = r0 + warp;
    const float4* __restrict__ crow =
        reinterpret_cast<const float4*>(mat + ((size_t)b * NN + row) * NN);
    const float4* swv = reinterpret_cast<const float4*>(sw);

    // Phase 0: front-batched loads (MLP = 16)
    float4 xv[16];
    #pragma unroll
    for (int k = 0; k < 16; k++)
        xv[k] = crow[lane + (k << 5)];

    // Phase 1: x = c*S + w, per-thread max tree
    float m0 = -1e30f, m1 = -1e30f, m2 = -1e30f, m3 = -1e30f;
    #pragma unroll
    for (int k = 0; k < 16; k++) {
        float4 w = swv[lane + (k << 5)];
        xv[k].x = fmaf(xv[k].x, SINK_S, w.x);
        xv[k].y = fmaf(xv[k].y, SINK_S, w.y);
        xv[k].z = fmaf(xv[k].z, SINK_S, w.z);
        xv[k].w = fmaf(xv[k].w, SINK_S, w.w);
        m0 = fmaxf(m0, xv[k].x);
        m1 = fmaxf(m1, xv[k].y);
        m2 = fmaxf(m2, xv[k].z);
        m3 = fmaxf(m3, xv[k].w);
    }
    float m = fmaxf(fmaxf(m0, m1), fmaxf(m2, m3));
    #pragma unroll
    for (int off = 16; off; off >>= 1)
        m = fmaxf(m, __shfl_xor_sync(0xffffffffu, m, off));

    // Phase 2: sum exp2(x - m), 4 independent accumulators
    float s0 = 0.f, s1 = 0.f, s2 = 0.f, s3 = 0.f;
    #pragma unroll
    for (int k = 0; k < 16; k++) {
        s0 += ex2f(xv[k].x - m);
        s1 += ex2f(xv[k].y - m);
        s2 += ex2f(xv[k].z - m);
        s3 += ex2f(xv[k].w - m);
    }
    float s = (s0 + s1) + (s2 + s3);
    #pragma unroll
    for (int off = 16; off; off >>= 1)
        s += __shfl_xor_sync(0xffffffffu, s, off);

    if (lane == 0) {
        float r = fmaf(-SINK_C1, m + lg2f(s), SINK_C0);
        if (!UPASS && r > 9e8f) r = 0.0f;   // reference clamp on v
        out[b * NN + row] = r;
    }
}

// ---- epilogue: pi = exp2((c+u+v)*S), -c, u, v ----
__global__ void __launch_bounds__(128) final_kernel(const float* __restrict__ c,
                                                    float* __restrict__ out) {
    const size_t BNN = (size_t)BB * NN * NN;
    const int rowid = blockIdx.x;
    const int b = rowid >> 11;
    const float u = g_u[rowid];
    const float4* __restrict__ crow =
        reinterpret_cast<const float4*>(c + (size_t)rowid * NN);
    const float4* __restrict__ vrow =
        reinterpret_cast<const float4*>(g_v + (size_t)b * NN);
    float4* pio = reinterpret_cast<float4*>(out + (size_t)rowid * NN);
    float4* nco = reinterpret_cast<float4*>(out + BNN + (size_t)rowid * NN);

    #pragma unroll 2
    for (int t = threadIdx.x; t < NN / 4; t += 128) {
        float4 cc = crow[t];
        float4 vv = vrow[t];
        float4 pi, nc;
        pi.x = ex2f(((cc.x + u) + vv.x) * SINK_S);
        pi.y = ex2f(((cc.y + u) + vv.y) * SINK_S);
        pi.z = ex2f(((cc.z + u) + vv.z) * SINK_S);
        pi.w = ex2f(((cc.w + u) + vv.w) * SINK_S);
        nc.x = -cc.x; nc.y = -cc.y; nc.z = -cc.z; nc.w = -cc.w;
        pio[t] = pi;
        nco[t] = nc;
    }
    int gid = blockIdx.x * 128 + threadIdx.x;
    if (gid < BB * NN) {
        out[2 * BNN + gid] = g_u[gid];
        out[2 * BNN + (size_t)BB * NN + gid] = g_v[gid];
    }
}

extern "C" void kernel_launch(void* const* d_in, const int* in_sizes, int n_in,
                              void* d_out, int out_size) {
    const float* c = (const float*)d_in[0];

    init_kernel<<<(BB * NN + 255) / 256, 256>>>();
    transpose_kernel<<<dim3(NN / 32, NN / 32, BB), dim3(32, 8)>>>(c);

    for (int it = 0; it < 50; ++it) {
        pass_kernel<true ><<<BB * (NN / 4), 128>>>(c);   // u-pass (reads c, g_v)
        pass_kernel<false><<<BB * (NN / 4), 128>>>(c);   // v-pass (reads g_ct, g_u)
    }
    final_kernel<<<BB * NN, 128>>>(c, (float*)d_out);
}

// round 6
// speedup vs baseline: 1.4477x; 1.0885x over previous
#include <cuda_runtime.h>
#include <cstdint>

// Sinkhorn: B=8, N=2048, eps=0.01, 50 fused (u,v) iterations.
//   u_i = eps*(log_mu - LSE_j((c_ij + v_j)/eps))   (old u cancels)
//   v_j = eps*(log_mu - LSE_i((c_ij + u_i)/eps))   (old v cancels)
// Base-2 domain: x = c*S + w*S, S = 1/(eps*ln2).
// R6: (a) chunked two-phase LSE (8 float4 per chunk) + launch_bounds(128,9)
//     to cut regs ~80 -> ~56 and raise occupancy ~33% -> ~56%;
//     (b) batches processed as 4 serialized pairs so each pass's working set
//     (c-pair 33.6MB + ct-pair 33.6MB = 67MB) stays L2-resident (126MB L2).
// All __device__ scratch referenced from device code only.
// Outputs: [pi (B*N*N), -c (B*N*N), u (B*N), v (B*N)]

#define NN 2048
#define BB 8
#define SINK_S  144.26950408889634f     // 1/(eps*ln2) = 100*log2(e)
#define SINK_C0 -0.07624618986159398f   // eps*log_mu = -0.01*ln(2048)
#define SINK_C1 0.006931471805599453f   // eps*ln2

__device__ float g_u[BB * NN];
__device__ float g_v[BB * NN];
__device__ float g_ct[(size_t)BB * NN * NN];   // c transposed per batch

__device__ __forceinline__ float ex2f(float x) {
    float r; asm("ex2.approx.f32 %0, %1;" : "=f"(r) : "f"(x)); return r;
}
__device__ __forceinline__ float lg2f(float x) {
    float r; asm("lg2.approx.f32 %0, %1;" : "=f"(r) : "f"(x)); return r;
}

__global__ void __launch_bounds__(256) init_kernel() {
    int i = blockIdx.x * 256 + threadIdx.x;
    if (i < BB * NN) g_v[i] = 0.0f;
}

// ---- transpose: g_ct[b][j][i] = c[b][i][j] ----
__global__ void __launch_bounds__(256) transpose_kernel(const float* __restrict__ c) {
    __shared__ float t[32][33];
    const int b = blockIdx.z;
    const size_t base = (size_t)b * NN * NN;
    const int x = blockIdx.x * 32 + threadIdx.x;
    const int y = blockIdx.y * 32 + threadIdx.y;
    #pragma unroll
    for (int j = 0; j < 32; j += 8)
        t[threadIdx.y + j][threadIdx.x] = c[base + (size_t)(y + j) * NN + x];
    __syncthreads();
    const int x2 = blockIdx.y * 32 + threadIdx.x;
    const int y2 = blockIdx.x * 32 + threadIdx.y;
    #pragma unroll
    for (int j = 0; j < 32; j += 8)
        g_ct[base + (size_t)(y2 + j) * NN + x2] = t[threadIdx.x][threadIdx.y + j];
}

// ---- LSE pass over rows. UPASS=true:  mat=c,    vec=g_v, out=g_u.
//                          UPASS=false: mat=g_ct, vec=g_u, out=g_v (clamped).
// Processes 2 batches per launch: b = b0 + (blockIdx.x >> 9).
template <bool UPASS>
__global__ void __launch_bounds__(128, 9) pass_kernel(const float* __restrict__ cmat,
                                                      int b0) {
    __shared__ float sw[NN];
    const int b  = b0 + (blockIdx.x >> 9);       // 512 CTAs per batch
    const int r0 = (blockIdx.x & 511) * 4;

    const float* vec = UPASS ? g_v : g_u;        // device-side symbol refs only
    const float* mat = UPASS ? cmat : g_ct;
    float*       out = UPASS ? g_u : g_v;

    {
        const float4* vv = reinterpret_cast<const float4*>(vec + b * NN);
        float4* sv = reinterpret_cast<float4*>(sw);
        #pragma unroll
        for (int t = threadIdx.x; t < NN / 4; t += 128) {
            float4 w = vv[t];
            w.x *= SINK_S; w.y *= SINK_S; w.z *= SINK_S; w.w *= SINK_S;
            sv[t] = w;
        }
    }
    __syncthreads();

    const int warp = threadIdx.x >> 5, lane = threadIdx.x & 31;
    const int row = r0 + warp;
    const float4* __restrict__ crow =
        reinterpret_cast<const float4*>(mat + ((size_t)b * NN + row) * NN);
    const float4* swv = reinterpret_cast<const float4*>(sw);

    float m = -1e30f, s = 0.0f;
    #pragma unroll
    for (int h = 0; h < 2; h++) {
        // Phase 0: front-batched loads for this chunk (MLP = 8)
        float4 xv[8];
        #pragma unroll
        for (int k = 0; k < 8; k++)
            xv[k] = crow[lane + ((h * 8 + k) << 5)];

        // Phase 1: x = c*S + w, chunk max tree
        float m0 = -1e30f, m1 = -1e30f, m2 = -1e30f, m3 = -1e30f;
        #pragma unroll
        for (int k = 0; k < 8; k++) {
            float4 w = swv[lane + ((h * 8 + k) << 5)];
            xv[k].x = fmaf(xv[k].x, SINK_S, w.x);
            xv[k].y = fmaf(xv[k].y, SINK_S, w.y);
            xv[k].z = fmaf(xv[k].z, SINK_S, w.z);
            xv[k].w = fmaf(xv[k].w, SINK_S, w.w);
            m0 = fmaxf(m0, xv[k].x);
            m1 = fmaxf(m1, xv[k].y);
            m2 = fmaxf(m2, xv[k].z);
            m3 = fmaxf(m3, xv[k].w);
        }
        float cm = fmaxf(fmaxf(m0, m1), fmaxf(m2, m3));

        // Phase 2: chunk exp2 sum, 4 independent accumulators
        float s0 = 0.f, s1 = 0.f, s2 = 0.f, s3 = 0.f;
        #pragma unroll
        for (int k = 0; k < 8; k++) {
            s0 += ex2f(xv[k].x - cm);
            s1 += ex2f(xv[k].y - cm);
            s2 += ex2f(xv[k].z - cm);
            s3 += ex2f(xv[k].w - cm);
        }
        float cs = (s0 + s1) + (s2 + s3);

        // combine chunk into running (m, s)
        float mm = fmaxf(m, cm);
        s = fmaf(s, ex2f(m - mm), cs * ex2f(cm - mm));
        m = mm;
    }

    // warp butterfly combine of (m, s)
    #pragma unroll
    for (int off = 16; off; off >>= 1) {
        float m2 = __shfl_xor_sync(0xffffffffu, m, off);
        float s2 = __shfl_xor_sync(0xffffffffu, s, off);
        float mm = fmaxf(m, m2);
        s = fmaf(s, ex2f(m - mm), s2 * ex2f(m2 - mm));
        m = mm;
    }

    if (lane == 0) {
        float r = fmaf(-SINK_C1, m + lg2f(s), SINK_C0);
        if (!UPASS && r > 9e8f) r = 0.0f;   // reference clamp on v
        out[b * NN + row] = r;
    }
}

// ---- epilogue: pi = exp2((c+u+v)*S), -c, u, v ----
__global__ void __launch_bounds__(128) final_kernel(const float* __restrict__ c,
                                                    float* __restrict__ out) {
    const size_t BNN = (size_t)BB * NN * NN;
    const int rowid = blockIdx.x;
    const int b = rowid >> 11;
    const float u = g_u[rowid];
    const float4* __restrict__ crow =
        reinterpret_cast<const float4*>(c + (size_t)rowid * NN);
    const float4* __restrict__ vrow =
        reinterpret_cast<const float4*>(g_v + (size_t)b * NN);
    float4* pio = reinterpret_cast<float4*>(out + (size_t)rowid * NN);
    float4* nco = reinterpret_cast<float4*>(out + BNN + (size_t)rowid * NN);

    #pragma unroll 2
    for (int t = threadIdx.x; t < NN / 4; t += 128) {
        float4 cc = crow[t];
        float4 vv = vrow[t];
        float4 pi, nc;
        pi.x = ex2f(((cc.x + u) + vv.x) * SINK_S);
        pi.y = ex2f(((cc.y + u) + vv.y) * SINK_S);
        pi.z = ex2f(((cc.z + u) + vv.z) * SINK_S);
        pi.w = ex2f(((cc.w + u) + vv.w) * SINK_S);
        nc.x = -cc.x; nc.y = -cc.y; nc.z = -cc.z; nc.w = -cc.w;
        pio[t] = pi;
        nco[t] = nc;
    }
    int gid = blockIdx.x * 128 + threadIdx.x;
    if (gid < BB * NN) {
        out[2 * BNN + gid] = g_u[gid];
        out[2 * BNN + (size_t)BB * NN + gid] = g_v[gid];
    }
}

extern "C" void kernel_launch(void* const* d_in, const int* in_sizes, int n_in,
                              void* d_out, int out_size) {
    const float* c = (const float*)d_in[0];

    init_kernel<<<(BB * NN + 255) / 256, 256>>>();
    transpose_kernel<<<dim3(NN / 32, NN / 32, BB), dim3(32, 8)>>>(c);

    // 4 serialized batch-pairs: per-pass working set 67MB -> L2-resident.
    for (int pr = 0; pr < 4; ++pr) {
        const int b0 = pr * 2;
        for (int it = 0; it < 50; ++it) {
            pass_kernel<true ><<<2 * (NN / 4), 128>>>(c, b0);   // u-pass
            pass_kernel<false><<<2 * (NN / 4), 128>>>(c, b0);   // v-pass
        }
    }
    final_kernel<<<BB * NN, 128>>>(c, (float*)d_out);
}